// round 1
// baseline (speedup 1.0000x reference)
#include <cuda_runtime.h>
#include <math.h>

#define E_TOT 102400
#define NGRAPH 64
#define D_IN   1408
#define H1     512
#define H2     512
#define H3     256

// Scratch (allocation-free rule: __device__ globals)
__device__ float g_Y1[(size_t)E_TOT * H1];   // 200 MB
__device__ float g_Y2[(size_t)E_TOT * H2];   // 200 MB
__device__ int   g_gcum[NGRAPH + 1];

// ---------------------------------------------------------------------------
// Kernel 0: prefix sum of num -> graph boundaries
// ---------------------------------------------------------------------------
__global__ void k_prefix(const int* __restrict__ num) {
    if (threadIdx.x == 0) {
        int s = 0;
        g_gcum[0] = 0;
        for (int i = 0; i < NGRAPH; i++) { s += num[i]; g_gcum[i + 1] = s; }
    }
}

// ---------------------------------------------------------------------------
// Kernel 1: Y1 = relu( X @ W1 + b1 ),  X gathered on the fly
//   X[e, k]:  k<256 -> feat ; 256..1279 -> nodes[ind[e][ (k-256)/256 ]] ;
//             1280..1407 -> gfeat[graph_id(e)]
// Tile: M=64, N=64, Kc=32. 256 threads, 4x4 per thread.
// ---------------------------------------------------------------------------
__global__ void __launch_bounds__(256) k_gemm1(
    const float* __restrict__ feat, const float* __restrict__ nodes,
    const float* __restrict__ gfeat, const int* __restrict__ ind,
    const float* __restrict__ W1, const float* __restrict__ b1)
{
    __shared__ float As[32][64];   // [k][m]
    __shared__ float Bs[32][64];   // [k][n]
    const int tid   = threadIdx.x;
    const int eBase = blockIdx.x * 64;
    const int nBase = blockIdx.y * 64;
    const int tx = tid & 15, ty = tid >> 4;

    float c[4][4] = {};

    for (int k0 = 0; k0 < D_IN; k0 += 32) {
        // ---- load A tile (gather) : 64 rows x 32 k = 512 float4
        #pragma unroll
        for (int i = 0; i < 2; i++) {
            int idx = tid * 2 + i;          // 0..511
            int row = idx >> 3;             // edge within tile
            int q   = idx & 7;              // float4 slot in k-chunk
            int e   = eBase + row;
            int k   = k0 + q * 4;
            const float* src;
            if (k < 256) {
                src = feat + (size_t)e * 256 + k;
            } else if (k < 1280) {
                int j   = (k - 256) >> 8;
                int nid = ind[e * 4 + j];
                src = nodes + (size_t)nid * 256 + ((k - 256) & 255);
            } else {
                int lo = 0, hi = NGRAPH;    // find g: gcum[g] <= e < gcum[g+1]
                while (hi - lo > 1) {
                    int mid = (lo + hi) >> 1;
                    if (g_gcum[mid] <= e) lo = mid; else hi = mid;
                }
                src = gfeat + (size_t)lo * 128 + (k - 1280);
            }
            float4 v = *(const float4*)src;
            As[q * 4 + 0][row] = v.x;
            As[q * 4 + 1][row] = v.y;
            As[q * 4 + 2][row] = v.z;
            As[q * 4 + 3][row] = v.w;
        }
        // ---- load B tile: 32 k x 64 n = 512 float4
        #pragma unroll
        for (int i = 0; i < 2; i++) {
            int idx = tid + 256 * i;        // 0..511
            int kk  = idx >> 4;             // 0..31
            int qn  = idx & 15;             // 0..15
            float4 v = *(const float4*)(W1 + (size_t)(k0 + kk) * H1 + nBase + qn * 4);
            *(float4*)(&Bs[kk][qn * 4]) = v;
        }
        __syncthreads();
        // ---- compute
        #pragma unroll
        for (int kk = 0; kk < 32; kk++) {
            float4 a = *(const float4*)(&As[kk][ty * 4]);
            float4 b = *(const float4*)(&Bs[kk][tx * 4]);
            float av[4] = {a.x, a.y, a.z, a.w};
            float bv[4] = {b.x, b.y, b.z, b.w};
            #pragma unroll
            for (int i = 0; i < 4; i++)
                #pragma unroll
                for (int j = 0; j < 4; j++)
                    c[i][j] = fmaf(av[i], bv[j], c[i][j]);
        }
        __syncthreads();
    }
    // ---- epilogue: bias + relu -> Y1
    #pragma unroll
    for (int i = 0; i < 4; i++) {
        int e = eBase + ty * 4 + i;
        int n = nBase + tx * 4;
        float4 o;
        o.x = fmaxf(c[i][0] + b1[n + 0], 0.f);
        o.y = fmaxf(c[i][1] + b1[n + 1], 0.f);
        o.z = fmaxf(c[i][2] + b1[n + 2], 0.f);
        o.w = fmaxf(c[i][3] + b1[n + 3], 0.f);
        *(float4*)(g_Y1 + (size_t)e * H1 + n) = o;
    }
}

// ---------------------------------------------------------------------------
// Kernel 2: Y2 = relu( Y1 @ W2 + b2 ).  Same tiling, plain A-load.
// ---------------------------------------------------------------------------
__global__ void __launch_bounds__(256) k_gemm2(
    const float* __restrict__ W2, const float* __restrict__ b2)
{
    __shared__ float As[32][64];
    __shared__ float Bs[32][64];
    const int tid   = threadIdx.x;
    const int eBase = blockIdx.x * 64;
    const int nBase = blockIdx.y * 64;
    const int tx = tid & 15, ty = tid >> 4;

    float c[4][4] = {};

    for (int k0 = 0; k0 < H1; k0 += 32) {
        #pragma unroll
        for (int i = 0; i < 2; i++) {
            int idx = tid * 2 + i;
            int row = idx >> 3;
            int q   = idx & 7;
            float4 v = *(const float4*)(g_Y1 + (size_t)(eBase + row) * H1 + k0 + q * 4);
            As[q * 4 + 0][row] = v.x;
            As[q * 4 + 1][row] = v.y;
            As[q * 4 + 2][row] = v.z;
            As[q * 4 + 3][row] = v.w;
        }
        #pragma unroll
        for (int i = 0; i < 2; i++) {
            int idx = tid + 256 * i;
            int kk  = idx >> 4;
            int qn  = idx & 15;
            float4 v = *(const float4*)(W2 + (size_t)(k0 + kk) * H2 + nBase + qn * 4);
            *(float4*)(&Bs[kk][qn * 4]) = v;
        }
        __syncthreads();
        #pragma unroll
        for (int kk = 0; kk < 32; kk++) {
            float4 a = *(const float4*)(&As[kk][ty * 4]);
            float4 b = *(const float4*)(&Bs[kk][tx * 4]);
            float av[4] = {a.x, a.y, a.z, a.w};
            float bv[4] = {b.x, b.y, b.z, b.w};
            #pragma unroll
            for (int i = 0; i < 4; i++)
                #pragma unroll
                for (int j = 0; j < 4; j++)
                    c[i][j] = fmaf(av[i], bv[j], c[i][j]);
        }
        __syncthreads();
    }
    #pragma unroll
    for (int i = 0; i < 4; i++) {
        int e = eBase + ty * 4 + i;
        int n = nBase + tx * 4;
        float4 o;
        o.x = fmaxf(c[i][0] + b2[n + 0], 0.f);
        o.y = fmaxf(c[i][1] + b2[n + 1], 0.f);
        o.z = fmaxf(c[i][2] + b2[n + 2], 0.f);
        o.w = fmaxf(c[i][3] + b2[n + 3], 0.f);
        *(float4*)(g_Y2 + (size_t)e * H2 + n) = o;
    }
}

// ---------------------------------------------------------------------------
// Kernel 3: out = LayerNorm( sigmoid( Y2 @ W3 + b3 ) ) * gamma + beta
// Tile: M=16, N=256 (full row -> LN in-block), Kc=32. 256 threads.
// Thread (m_t = tid/32 owns rows m_t*2..+1; n_t = tid%32 owns cols n_t*8..+7)
// A warp covers exactly one m_t => row reductions are warp-shuffles.
// ---------------------------------------------------------------------------
__global__ void __launch_bounds__(256) k_gemm3(
    const float* __restrict__ W3, const float* __restrict__ b3,
    const float* __restrict__ gamma, const float* __restrict__ beta,
    float* __restrict__ out)
{
    __shared__ float As[32][16];    // [k][m]
    __shared__ float Bs[32][256];   // [k][n]
    const int tid   = threadIdx.x;
    const int eBase = blockIdx.x * 16;
    const int n_t = tid & 31;
    const int m_t = tid >> 5;

    float c[2][8] = {};

    for (int k0 = 0; k0 < H2; k0 += 32) {
        if (tid < 128) {            // 16 rows x 8 float4
            int row = tid >> 3;
            int q   = tid & 7;
            float4 v = *(const float4*)(g_Y2 + (size_t)(eBase + row) * H2 + k0 + q * 4);
            As[q * 4 + 0][row] = v.x;
            As[q * 4 + 1][row] = v.y;
            As[q * 4 + 2][row] = v.z;
            As[q * 4 + 3][row] = v.w;
        }
        #pragma unroll
        for (int i = 0; i < 8; i++) {
            int idx = tid + 256 * i;    // 0..2047
            int kk  = idx >> 6;         // 0..31
            int qn  = idx & 63;         // 0..63
            *(float4*)(&Bs[kk][qn * 4]) =
                *(const float4*)(W3 + (size_t)(k0 + kk) * H3 + qn * 4);
        }
        __syncthreads();
        #pragma unroll
        for (int kk = 0; kk < 32; kk++) {
            float2 a = *(const float2*)(&As[kk][m_t * 2]);
            float4 b0 = *(const float4*)(&Bs[kk][n_t * 8]);
            float4 b1v = *(const float4*)(&Bs[kk][n_t * 8 + 4]);
            float bv[8] = {b0.x, b0.y, b0.z, b0.w, b1v.x, b1v.y, b1v.z, b1v.w};
            #pragma unroll
            for (int j = 0; j < 8; j++) {
                c[0][j] = fmaf(a.x, bv[j], c[0][j]);
                c[1][j] = fmaf(a.y, bv[j], c[1][j]);
            }
        }
        __syncthreads();
    }

    // epilogue: bias + sigmoid + LayerNorm(256) + affine
    #pragma unroll
    for (int i = 0; i < 2; i++) {
        int e = eBase + m_t * 2 + i;
        float h[8];
        float s = 0.f, sq = 0.f;
        #pragma unroll
        for (int j = 0; j < 8; j++) {
            float x = c[i][j] + b3[n_t * 8 + j];
            float v = 1.f / (1.f + expf(-x));
            h[j] = v;
            s += v;
            sq += v * v;
        }
        #pragma unroll
        for (int o = 16; o > 0; o >>= 1) {
            s  += __shfl_xor_sync(0xFFFFFFFFu, s,  o);
            sq += __shfl_xor_sync(0xFFFFFFFFu, sq, o);
        }
        float mu  = s * (1.f / 256.f);
        float var = sq * (1.f / 256.f) - mu * mu;
        float rs  = rsqrtf(var + 1e-3f);
        float4 o0, o1;
        {
            int n = n_t * 8;
            o0.x = gamma[n + 0] * (h[0] - mu) * rs + beta[n + 0];
            o0.y = gamma[n + 1] * (h[1] - mu) * rs + beta[n + 1];
            o0.z = gamma[n + 2] * (h[2] - mu) * rs + beta[n + 2];
            o0.w = gamma[n + 3] * (h[3] - mu) * rs + beta[n + 3];
            o1.x = gamma[n + 4] * (h[4] - mu) * rs + beta[n + 4];
            o1.y = gamma[n + 5] * (h[5] - mu) * rs + beta[n + 5];
            o1.z = gamma[n + 6] * (h[6] - mu) * rs + beta[n + 6];
            o1.w = gamma[n + 7] * (h[7] - mu) * rs + beta[n + 7];
        }
        *(float4*)(out + (size_t)e * H3 + n_t * 8)     = o0;
        *(float4*)(out + (size_t)e * H3 + n_t * 8 + 4) = o1;
    }
}

// ---------------------------------------------------------------------------
extern "C" void kernel_launch(void* const* d_in, const int* in_sizes, int n_in,
                              void* d_out, int out_size)
{
    const float* feat  = (const float*)d_in[0];
    const float* nodes = (const float*)d_in[1];
    const float* gfeat = (const float*)d_in[2];
    const int*   ind   = (const int*)  d_in[3];
    const int*   num   = (const int*)  d_in[4];
    const float* W1    = (const float*)d_in[5];
    const float* b1    = (const float*)d_in[6];
    const float* W2    = (const float*)d_in[7];
    const float* b2    = (const float*)d_in[8];
    const float* W3    = (const float*)d_in[9];
    const float* b3    = (const float*)d_in[10];
    const float* gamma = (const float*)d_in[11];
    const float* beta  = (const float*)d_in[12];
    float* out = (float*)d_out;

    k_prefix<<<1, 32>>>(num);

    dim3 g1(E_TOT / 64, H1 / 64);
    k_gemm1<<<g1, 256>>>(feat, nodes, gfeat, ind, W1, b1);

    dim3 g2(E_TOT / 64, H2 / 64);
    k_gemm2<<<g2, 256>>>(W2, b2);

    k_gemm3<<<E_TOT / 16, 256>>>(W3, b3, gamma, beta, out);
}

// round 4
// speedup vs baseline: 3.7514x; 3.7514x over previous
#include <cuda_runtime.h>
#include <cstdint>
#include <math.h>

#define E_TOT 102400
#define NGRAPH 64
#define D_IN   1408
#define H1     512
#define H2     512
#define H3     256

// ---------------- scratch (__device__ globals; no allocs allowed) ----------
__device__ float g_Y1[(size_t)E_TOT * H1];   // also reused as H (sigmoid out) for layer 3
__device__ float g_Y2[(size_t)E_TOT * H2];
__device__ int   g_gcum[NGRAPH + 1];

// ---------------- helpers ---------------------------------------------------
#define CP_ASYNC16(dst, src) \
    asm volatile("cp.async.cg.shared.global [%0], [%1], 16;" :: "r"(dst), "l"(src) : "memory")
#define CP_COMMIT() asm volatile("cp.async.commit_group;" ::: "memory")
#define CP_WAIT(n)  asm volatile("cp.async.wait_group %0;" :: "n"(n) : "memory")

__device__ __forceinline__ uint32_t smem_u32(const void* p) {
    uint32_t a;
    asm("{ .reg .u64 t; cvta.to.shared.u64 t, %1; cvt.u32.u64 %0, t; }"
        : "=r"(a) : "l"(p));
    return a;
}

// m16n8k8 tf32 mma: D(16x8,f32) += A(16x8,tf32) * B(8x8,tf32)
__device__ __forceinline__ void mma_tf32(float* c, const uint32_t* a,
                                         uint32_t b0, uint32_t b1) {
    asm volatile(
        "mma.sync.aligned.m16n8k8.row.col.f32.tf32.tf32.f32 "
        "{%0,%1,%2,%3}, {%4,%5,%6,%7}, {%8,%9}, {%0,%1,%2,%3};"
        : "+f"(c[0]), "+f"(c[1]), "+f"(c[2]), "+f"(c[3])
        : "r"(a[0]), "r"(a[1]), "r"(a[2]), "r"(a[3]), "r"(b0), "r"(b1));
}

// ---------------- Kernel 0: prefix sum of num -------------------------------
__global__ void k_prefix(const int* __restrict__ num) {
    if (threadIdx.x == 0) {
        int s = 0;
        g_gcum[0] = 0;
        for (int i = 0; i < NGRAPH; i++) { s += num[i]; g_gcum[i + 1] = s; }
    }
}

// ---------------- tiled tf32 GEMM -------------------------------------------
// Tile: BM=128, BN=128, BK=32. 256 threads = 8 warps (4 M x 2 N), warp tile 32x64.
// MODE 0: A gathered (feat | nodes[ind] | gfeat);  MODE 1: A dense [E][KDIM].
// EPI  0: relu(x + bias);  EPI 1: sigmoid(x + bias).  Output: Yout[E][HOUT].
template<int KDIM, int MODE, int EPI, int HOUT>
__global__ void __launch_bounds__(256) gemm_mma(
    const float* __restrict__ Af, const float* __restrict__ nodes,
    const float* __restrict__ gfeat, const int* __restrict__ ind,
    const float* __restrict__ W, const float* __restrict__ bias,
    float* __restrict__ Yout)
{
    constexpr int BM = 128, BN = 128, BK = 32;
    constexpr int PA = 36;    // A smem row stride (floats): 36 % 32 == 4 -> conflict-free frags
    constexpr int PB = 136;   // B smem row stride (floats): 136 % 32 == 8 -> conflict-free frags
    constexpr int STAGEF = BM * PA + BK * PB;        // floats per stage
    constexpr int NC = KDIM / BK;

    extern __shared__ float sm[];

    const int tid  = threadIdx.x;
    const int wid  = tid >> 5;
    const int lane = tid & 31;
    const int warpM = wid & 3;       // 0..3
    const int warpN = wid >> 2;      // 0..1
    const int eBase = blockIdx.x * BM;
    const int nBase = blockIdx.y * BN;

    const int grp = lane >> 2;       // 0..7
    const int tig = lane & 3;        // 0..3

    float acc[2][8][4];
    #pragma unroll
    for (int i = 0; i < 2; i++)
        #pragma unroll
        for (int j = 0; j < 8; j++)
            #pragma unroll
            for (int u = 0; u < 4; u++) acc[i][j][u] = 0.f;

    // ---- chunk loader ------------------------------------------------------
    // A: 128 rows x 32 floats. 2 threads/row, each 4 x cp.async(16B).
    // B: 32 rows x 128 floats. idx = tid + 256*i: krow = idx>>5, col4 = idx&31.
    const int arow  = tid >> 1;
    const int ahalf = (tid & 1) * 16;

    auto load_chunk = [&](int c) {
        float* As = sm + (c & 1) * STAGEF;
        float* Bs = As + BM * PA;
        const int k0 = c * BK;
        // ---- A
        const float* asrc;
        if (MODE == 0) {
            const int e = eBase + arow;
            const int k = k0 + ahalf;
            if (k < 256) {
                asrc = Af + (size_t)e * 256 + k;
            } else if (k < 1280) {
                const int j   = (k - 256) >> 8;
                const int nid = __ldg(ind + e * 4 + j);
                asrc = nodes + (size_t)nid * 256 + ((k - 256) & 255);
            } else {
                int lo = 0, hi = NGRAPH;
                while (hi - lo > 1) {
                    int mid = (lo + hi) >> 1;
                    if (g_gcum[mid] <= e) lo = mid; else hi = mid;
                }
                asrc = gfeat + (size_t)lo * 128 + (k - 1280);
            }
        } else {
            asrc = Af + (size_t)(eBase + arow) * KDIM + k0 + ahalf;
        }
        uint32_t adst = smem_u32(As + arow * PA + ahalf);
        #pragma unroll
        for (int q = 0; q < 4; q++)
            CP_ASYNC16(adst + q * 16, asrc + q * 4);
        // ---- B
        #pragma unroll
        for (int i = 0; i < 4; i++) {
            const int idx  = tid + 256 * i;
            const int krow = idx >> 5;
            const int col4 = idx & 31;
            const float* bsrc = W + (size_t)(k0 + krow) * HOUT + nBase + col4 * 4;
            uint32_t bdst = smem_u32(Bs + krow * PB + col4 * 4);
            CP_ASYNC16(bdst, bsrc);
        }
        CP_COMMIT();
    };

    load_chunk(0);

    for (int c = 0; c < NC; c++) {
        if (c + 1 < NC) {
            load_chunk(c + 1);
            CP_WAIT(1);
        } else {
            CP_WAIT(0);
        }
        __syncthreads();

        const uint32_t* As = (const uint32_t*)(sm + (c & 1) * STAGEF);
        const uint32_t* Bs = As + BM * PA;

        #pragma unroll
        for (int ks = 0; ks < 4; ks++) {
            const int kb = ks * 8;
            uint32_t a[2][4];
            #pragma unroll
            for (int mi = 0; mi < 2; mi++) {
                const int m = warpM * 32 + mi * 16 + grp;
                const int k = kb + tig;
                a[mi][0] = As[m * PA + k];
                a[mi][1] = As[(m + 8) * PA + k];
                a[mi][2] = As[m * PA + k + 4];
                a[mi][3] = As[(m + 8) * PA + k + 4];
            }
            #pragma unroll
            for (int ni = 0; ni < 8; ni++) {
                const int n = warpN * 64 + ni * 8 + grp;
                const uint32_t b0 = Bs[(kb + tig) * PB + n];
                const uint32_t b1 = Bs[(kb + tig + 4) * PB + n];
                mma_tf32(acc[0][ni], a[0], b0, b1);
                mma_tf32(acc[1][ni], a[1], b0, b1);
            }
        }
        __syncthreads();
    }

    // ---- epilogue: bias + activation -> Yout ------------------------------
    #pragma unroll
    for (int ni = 0; ni < 8; ni++) {
        const int col = nBase + warpN * 64 + ni * 8 + tig * 2;
        const float2 bb = *(const float2*)(bias + col);
        #pragma unroll
        for (int mi = 0; mi < 2; mi++) {
            const int e0 = eBase + warpM * 32 + mi * 16 + grp;
            #pragma unroll
            for (int h = 0; h < 2; h++) {       // rows e0, e0+8
                float x0 = acc[mi][ni][h * 2 + 0] + bb.x;
                float x1 = acc[mi][ni][h * 2 + 1] + bb.y;
                float2 v;
                if (EPI == 0) {
                    v.x = fmaxf(x0, 0.f);
                    v.y = fmaxf(x1, 0.f);
                } else {
                    v.x = 1.f / (1.f + __expf(-x0));
                    v.y = 1.f / (1.f + __expf(-x1));
                }
                *(float2*)(Yout + (size_t)(e0 + h * 8) * HOUT + col) = v;
            }
        }
    }
}

// ---------------- LayerNorm over last dim (256) ------------------------------
__global__ void __launch_bounds__(256) k_ln(
    const float* __restrict__ H, const float* __restrict__ gamma,
    const float* __restrict__ beta, float* __restrict__ out)
{
    const int row  = blockIdx.x * 8 + (threadIdx.x >> 5);
    const int lane = threadIdx.x & 31;
    const float* hp = H + (size_t)row * 256 + lane * 8;
    float4 v0 = *(const float4*)(hp);
    float4 v1 = *(const float4*)(hp + 4);
    float s  = v0.x + v0.y + v0.z + v0.w + v1.x + v1.y + v1.z + v1.w;
    float sq = v0.x*v0.x + v0.y*v0.y + v0.z*v0.z + v0.w*v0.w
             + v1.x*v1.x + v1.y*v1.y + v1.z*v1.z + v1.w*v1.w;
    #pragma unroll
    for (int o = 16; o > 0; o >>= 1) {
        s  += __shfl_xor_sync(0xFFFFFFFFu, s,  o);
        sq += __shfl_xor_sync(0xFFFFFFFFu, sq, o);
    }
    const float mu  = s * (1.f / 256.f);
    const float var = sq * (1.f / 256.f) - mu * mu;
    const float rs  = rsqrtf(var + 1e-3f);
    const float4 g0 = *(const float4*)(gamma + lane * 8);
    const float4 g1 = *(const float4*)(gamma + lane * 8 + 4);
    const float4 b0 = *(const float4*)(beta + lane * 8);
    const float4 b1 = *(const float4*)(beta + lane * 8 + 4);
    float4 o0, o1;
    o0.x = g0.x * (v0.x - mu) * rs + b0.x;
    o0.y = g0.y * (v0.y - mu) * rs + b0.y;
    o0.z = g0.z * (v0.z - mu) * rs + b0.z;
    o0.w = g0.w * (v0.w - mu) * rs + b0.w;
    o1.x = g1.x * (v1.x - mu) * rs + b1.x;
    o1.y = g1.y * (v1.y - mu) * rs + b1.y;
    o1.z = g1.z * (v1.z - mu) * rs + b1.z;
    o1.w = g1.w * (v1.w - mu) * rs + b1.w;
    float* op = out + (size_t)row * 256 + lane * 8;
    *(float4*)(op)     = o0;
    *(float4*)(op + 4) = o1;
}

// ---------------------------------------------------------------------------
extern "C" void kernel_launch(void* const* d_in, const int* in_sizes, int n_in,
                              void* d_out, int out_size)
{
    const float* feat  = (const float*)d_in[0];
    const float* nodes = (const float*)d_in[1];
    const float* gfeat = (const float*)d_in[2];
    const int*   ind   = (const int*)  d_in[3];
    const int*   num   = (const int*)  d_in[4];
    const float* W1    = (const float*)d_in[5];
    const float* b1    = (const float*)d_in[6];
    const float* W2    = (const float*)d_in[7];
    const float* b2    = (const float*)d_in[8];
    const float* W3    = (const float*)d_in[9];
    const float* b3    = (const float*)d_in[10];
    const float* gamma = (const float*)d_in[11];
    const float* beta  = (const float*)d_in[12];
    float* out = (float*)d_out;

    constexpr int PA = 36, PB = 136;
    const int SMEM_BYTES = 2 * (128 * PA + 32 * PB) * 4;   // 71680

    cudaFuncSetAttribute(gemm_mma<D_IN, 0, 0, H1>,
                         cudaFuncAttributeMaxDynamicSharedMemorySize, SMEM_BYTES);
    cudaFuncSetAttribute(gemm_mma<H1, 1, 0, H2>,
                         cudaFuncAttributeMaxDynamicSharedMemorySize, SMEM_BYTES);
    cudaFuncSetAttribute(gemm_mma<H2, 1, 1, H3>,
                         cudaFuncAttributeMaxDynamicSharedMemorySize, SMEM_BYTES);

    float* Y1; cudaGetSymbolAddress((void**)&Y1, g_Y1);
    float* Y2; cudaGetSymbolAddress((void**)&Y2, g_Y2);

    k_prefix<<<1, 32>>>(num);

    gemm_mma<D_IN, 0, 0, H1><<<dim3(E_TOT / 128, H1 / 128), 256, SMEM_BYTES>>>(
        feat, nodes, gfeat, ind, W1, b1, Y1);

    gemm_mma<H1, 1, 0, H2><<<dim3(E_TOT / 128, H2 / 128), 256, SMEM_BYTES>>>(
        Y1, nullptr, nullptr, nullptr, W2, b2, Y2);

    gemm_mma<H2, 1, 1, H3><<<dim3(E_TOT / 128, H3 / 128), 256, SMEM_BYTES>>>(
        Y2, nullptr, nullptr, nullptr, W3, b3, Y1);

    k_ln<<<E_TOT / 8, 256>>>(Y1, gamma, beta, out);
}